// round 6
// baseline (speedup 1.0000x reference)
#include <cuda_runtime.h>
#include <cuda_bf16.h>
#include <stdint.h>

// Problem sizes
#define N_TOK   16384     // 16 * 32 * 32
#define E_DIM   256
#define N_E     8192
#define ZQ_ELEMS (N_TOK * E_DIM)   // 4194304
// d_out layout (float32): [ z_q : ZQ_ELEMS ][ loss : 1 ][ idx : N_TOK ]

// ---------------- scratch (no runtime allocation allowed) ----------------
__device__ float g_zt[N_TOK * E_DIM];   // z transposed to [n][c], 16 MB
__device__ float g_znorm[N_TOK];
__device__ float g_enorm[N_E];
__device__ int   g_idx[N_TOK];
__device__ float g_loss;

// ---------------- K1: transpose z [16,256,32,32] -> zt [16384,256] -------
__global__ void transpose_kernel(const float* __restrict__ z) {
    __shared__ float t[32][33];
    int b   = blockIdx.z;
    int c0  = blockIdx.y * 32;
    int hw0 = blockIdx.x * 32;
    int tx = threadIdx.x, ty = threadIdx.y;

    if (blockIdx.x == 0 && blockIdx.y == 0 && blockIdx.z == 0 && tx == 0 && ty == 0)
        g_loss = 0.f;

    #pragma unroll
    for (int i = ty; i < 32; i += 8)
        t[i][tx] = z[((b * 256 + c0 + i) << 10) + hw0 + tx];
    __syncthreads();
    #pragma unroll
    for (int i = ty; i < 32; i += 8)
        g_zt[(b * 1024 + hw0 + i) * 256 + c0 + tx] = t[tx][i];
}

// ---------------- K1b: row norms (warp per row) --------------------------
// 8 warps per 256-thread block; need N_TOK + N_E = 24576 warps -> 3072 blocks.
__global__ void norms_kernel(const float* __restrict__ emb) {
    int gw   = (blockIdx.x * blockDim.x + threadIdx.x) >> 5;
    int lane = threadIdx.x & 31;
    const float* src;
    float* dst;
    if (gw < N_TOK)              { src = g_zt + gw * 256;           dst = g_znorm + gw; }
    else if (gw < N_TOK + N_E)   { src = emb  + (gw - N_TOK) * 256; dst = g_enorm + (gw - N_TOK); }
    else return;

    const float4* p = (const float4*)src;
    float s = 0.f;
    #pragma unroll
    for (int i = 0; i < 2; i++) {
        float4 v = p[lane + 32 * i];
        s = fmaf(v.x, v.x, s); s = fmaf(v.y, v.y, s);
        s = fmaf(v.z, v.z, s); s = fmaf(v.w, v.w, s);
    }
    #pragma unroll
    for (int o = 16; o; o >>= 1) s += __shfl_xor_sync(0xFFFFFFFFu, s, o);
    if (lane == 0) *dst = s;
}

// ---------------- K2: fused GEMM + argmin --------------------------------
// Block: 128 rows x all 8192 codes (64 tiles of 128). 256 threads, 8x8 microtile.
#define BM 128
#define BN 128
#define BK 8

__device__ __forceinline__ unsigned f2o(float f) {
    unsigned u = __float_as_uint(f);
    return (u & 0x80000000u) ? ~u : (u | 0x80000000u);
}

__global__ __launch_bounds__(256, 2)
void vq_argmin_kernel(const float* __restrict__ emb, float* __restrict__ out_idx_f) {
    __shared__ float As[2][BK][BM + 4];
    __shared__ float Bs[2][BK][BN + 4];
    __shared__ unsigned long long sKey[BM];

    int tid  = threadIdx.x;
    int row0 = blockIdx.x * BM;
    for (int i = tid; i < BM; i += 256) sKey[i] = 0xFFFFFFFFFFFFFFFFull;

    int tx = tid & 15;       // col group
    int ty = tid >> 4;       // row group
    int lr = tid >> 1;       // load row (0..127)
    int lj = (tid & 1) * 4;  // load k-offset in stage

    float zn[8];
    #pragma unroll
    for (int i = 0; i < 8; i++) zn[i] = g_znorm[row0 + ty * 8 + i];

    for (int ct = 0; ct < N_E / BN; ct++) {
        int c0 = ct * BN;
        float acc[8][8];
        #pragma unroll
        for (int i = 0; i < 8; i++)
            #pragma unroll
            for (int j = 0; j < 8; j++) acc[i][j] = 0.f;

        // stage 0
        float4 aReg = *(const float4*)&g_zt[(row0 + lr) * 256 + lj];
        float4 bReg = *(const float4*)&emb [(c0   + lr) * 256 + lj];
        As[0][lj + 0][lr] = aReg.x; As[0][lj + 1][lr] = aReg.y;
        As[0][lj + 2][lr] = aReg.z; As[0][lj + 3][lr] = aReg.w;
        Bs[0][lj + 0][lr] = bReg.x; Bs[0][lj + 1][lr] = bReg.y;
        Bs[0][lj + 2][lr] = bReg.z; Bs[0][lj + 3][lr] = bReg.w;
        __syncthreads();

        int cur = 0;
        #pragma unroll 1
        for (int ks = 0; ks < E_DIM / BK; ks++) {
            if (ks < E_DIM / BK - 1) {
                aReg = *(const float4*)&g_zt[(row0 + lr) * 256 + (ks + 1) * BK + lj];
                bReg = *(const float4*)&emb [(c0   + lr) * 256 + (ks + 1) * BK + lj];
            }
            #pragma unroll
            for (int k = 0; k < BK; k++) {
                float a[8], bf[8];
                *(float4*)(&a[0])  = *(const float4*)(&As[cur][k][ty * 8]);
                *(float4*)(&a[4])  = *(const float4*)(&As[cur][k][ty * 8 + 4]);
                *(float4*)(&bf[0]) = *(const float4*)(&Bs[cur][k][tx * 8]);
                *(float4*)(&bf[4]) = *(const float4*)(&Bs[cur][k][tx * 8 + 4]);
                #pragma unroll
                for (int i = 0; i < 8; i++)
                    #pragma unroll
                    for (int j = 0; j < 8; j++)
                        acc[i][j] = fmaf(a[i], bf[j], acc[i][j]);
            }
            if (ks < E_DIM / BK - 1) {
                int nxt = cur ^ 1;
                As[nxt][lj + 0][lr] = aReg.x; As[nxt][lj + 1][lr] = aReg.y;
                As[nxt][lj + 2][lr] = aReg.z; As[nxt][lj + 3][lr] = aReg.w;
                Bs[nxt][lj + 0][lr] = bReg.x; Bs[nxt][lj + 1][lr] = bReg.y;
                Bs[nxt][lj + 2][lr] = bReg.z; Bs[nxt][lj + 3][lr] = bReg.w;
                __syncthreads();
                cur = nxt;
            }
        }

        // epilogue: score = fl(fl(zn+en) - 2*dot), running (score, idx) min
        #pragma unroll
        for (int i = 0; i < 8; i++) {
            float best = __int_as_float(0x7F800000);  // +inf
            unsigned bestIdx = 0;
            #pragma unroll
            for (int j = 0; j < 8; j++) {
                int c = c0 + tx * 8 + j;
                float s = zn[i] + __ldg(&g_enorm[c]);
                s = fmaf(-2.f, acc[i][j], s);
                if (s < best) { best = s; bestIdx = (unsigned)c; }
            }
            unsigned long long key = ((unsigned long long)f2o(best) << 32) | bestIdx;
            atomicMin(&sKey[ty * 8 + i], key);
        }
        __syncthreads();
    }

    if (tid < BM) {
        unsigned long long key = sKey[tid];
        int idx = (int)(unsigned)(key & 0xFFFFFFFFull);
        g_idx[row0 + tid] = idx;
        out_idx_f[row0 + tid] = (float)idx;
    }
}

// ---------------- K3: gather z_q to [b,c,h,w] + loss ---------------------
// 512 blocks = (b,h); 1024 threads = 32 warps, warp w handles pixel (b,h,w)
__global__ void epilogue_kernel(const float* __restrict__ emb, float* __restrict__ out) {
    int bh = blockIdx.x;
    int b = bh >> 5, h = bh & 31;
    int w    = threadIdx.x >> 5;
    int lane = threadIdx.x & 31;
    int n = (b << 10) + (h << 5) + w;
    int idx = g_idx[n];

    const float4* ep = (const float4*)(emb  + idx * 256);
    const float4* zp = (const float4*)(g_zt + n   * 256);
    float ls = 0.f;
    #pragma unroll
    for (int i = 0; i < 2; i++) {
        float4 e  = ep[lane + 32 * i];
        float4 zv = zp[lane + 32 * i];
        int c = (lane + 32 * i) * 4;
        int base = (b * 256 + c) * 1024 + h * 32 + w;
        out[base]        = e.x;
        out[base + 1024] = e.y;
        out[base + 2048] = e.z;
        out[base + 3072] = e.w;
        float dx = e.x - zv.x, dy = e.y - zv.y, dz = e.z - zv.z, dw = e.w - zv.w;
        ls += dx * dx + dy * dy + dz * dz + dw * dw;
    }
    #pragma unroll
    for (int o = 16; o; o >>= 1) ls += __shfl_xor_sync(0xFFFFFFFFu, ls, o);
    __shared__ float red[32];
    if (lane == 0) red[w] = ls;
    __syncthreads();
    if (threadIdx.x < 32) {
        float v = red[threadIdx.x];
        #pragma unroll
        for (int o = 16; o; o >>= 1) v += __shfl_xor_sync(0xFFFFFFFFu, v, o);
        if (threadIdx.x == 0) atomicAdd(&g_loss, v);
    }
}

__global__ void finalize_kernel(float* __restrict__ out_loss) {
    out_loss[0] = 1.25f * g_loss * (1.0f / (float)ZQ_ELEMS);
}

// ---------------- launch --------------------------------------------------
extern "C" void kernel_launch(void* const* d_in, const int* in_sizes, int n_in,
                              void* d_out, int out_size) {
    const float* z   = (const float*)d_in[0];
    const float* emb = (const float*)d_in[1];
    float* out = (float*)d_out;

    transpose_kernel<<<dim3(32, 8, 16), dim3(32, 8)>>>(z);
    // 24576 row-norm warps, 8 warps per block -> 3072 blocks (FIXED: was 12)
    norms_kernel<<<(N_TOK + N_E) / 8, 256>>>(emb);
    vq_argmin_kernel<<<N_TOK / BM, 256>>>(emb, out + ZQ_ELEMS + 1);
    epilogue_kernel<<<512, 1024>>>(emb, out);
    finalize_kernel<<<1, 1>>>(out + ZQ_ELEMS);
}

// round 8
// speedup vs baseline: 1.8538x; 1.8538x over previous
#include <cuda_runtime.h>
#include <cuda_bf16.h>
#include <stdint.h>

// Problem sizes
#define N_TOK   16384
#define E_DIM   256
#define N_E     8192
#define ZQ_ELEMS (N_TOK * E_DIM)
// d_out layout (float32): [ z_q : ZQ_ELEMS ][ loss : 1 ][ idx : N_TOK ]

// GEMM config: C[16384, 8192], K' = 768 (3-term tf32 emulation folded into K)
#define BM 128
#define BN 256
#define NT (N_E / BN)          // 32 n-tiles
#define KP 768                 // 96 k8-blocks
#define NCHUNK 24              // K' staged in 24 chunks of 32
#define TOTAL_GC (NT * NCHUNK) // 768 global chunks

// smem: 2 stages x (A 128x32 + B 256x32) floats = 2 x 12288 floats = 96 KB
#define STAGE_F  12288
#define A_F      4096          // A floats per stage
#define SMEM_DYN (2 * STAGE_F * 4)

// ---------------- scratch ----------------
__device__ float g_zt[N_TOK * E_DIM];            // exact z, [n][c]
__device__ float g_za[96 * N_TOK * 8];           // A' [kb][m][8perm]  48 MB
__device__ float g_eb[96 * N_E * 8];             // B' [kb][n][8perm]  24 MB
__device__ float g_znorm[N_TOK];
__device__ float g_enorm[N_E];
__device__ int   g_idx[N_TOK];
__device__ float g_loss;

// ---------------- helpers ----------------
__device__ __forceinline__ uint32_t smem_to_u32(const void* p) {
    uint32_t a;
    asm("{ .reg .u64 t; cvta.to.shared.u64 t, %1; cvt.u32.u64 %0, t; }" : "=r"(a) : "l"(p));
    return a;
}
__device__ __forceinline__ float tf32_rna(float x) {
    uint32_t u;
    asm("cvt.rna.tf32.f32 %0, %1;" : "=r"(u) : "f"(x));
    return __uint_as_float(u);
}
__device__ __forceinline__ unsigned f2o(float f) {
    unsigned u = __float_as_uint(f);
    return (u & 0x80000000u) ? ~u : (u | 0x80000000u);
}
__device__ __forceinline__ void cpasync16(uint32_t dst, const void* src) {
    asm volatile("cp.async.cg.shared.global [%0], [%1], 16;" :: "r"(dst), "l"(src));
}
#define CP_COMMIT()  asm volatile("cp.async.commit_group;" ::: "memory")
#define CP_WAIT(n)   asm volatile("cp.async.wait_group %0;" :: "n"(n) : "memory")

#define MMA_TF32(d, a0, a1, a2, a3, b0, b1) \
    asm volatile("mma.sync.aligned.m16n8k8.row.col.f32.tf32.tf32.f32 " \
        "{%0,%1,%2,%3}, {%4,%5,%6,%7}, {%8,%9}, {%0,%1,%2,%3};" \
        : "+f"((d)[0]), "+f"((d)[1]), "+f"((d)[2]), "+f"((d)[3]) \
        : "r"(a0), "r"(a1), "r"(a2), "r"(a3), "r"(b0), "r"(b1))

// column permutation for LDS.64 fragment loads: position p holds col perm[p],
// perm = [0,4,1,5,2,6,3,7];  pos(c) = (c&3)*2 + (c>>2)
__device__ __forceinline__ int cpos(int c) { return ((c & 3) << 1) | (c >> 2); }

// ---------------- K1: transpose z + build A' ----------------
// A' regions: kb [0,32): z_hi ; [32,64): z_lo ; [64,96): z_hi
__global__ void transpose_kernel(const float* __restrict__ z) {
    __shared__ float t[32][33];
    int b   = blockIdx.z;
    int c0  = blockIdx.y * 32;
    int hw0 = blockIdx.x * 32;
    int tx = threadIdx.x, ty = threadIdx.y;

    if (blockIdx.x == 0 && blockIdx.y == 0 && blockIdx.z == 0 && tx == 0 && ty == 0)
        g_loss = 0.f;

    #pragma unroll
    for (int i = ty; i < 32; i += 8)
        t[i][tx] = z[((b * 256 + c0 + i) << 10) + hw0 + tx];
    __syncthreads();
    #pragma unroll
    for (int i = ty; i < 32; i += 8) {
        float v = t[tx][i];
        int m = b * 1024 + hw0 + i;
        int k = c0 + tx;
        g_zt[m * 256 + k] = v;
        float hi = tf32_rna(v);
        float lo = tf32_rna(v - hi);
        int kb = k >> 3;
        int base = (kb * N_TOK + m) * 8 + cpos(k & 7);
        g_za[base]                    = hi;   // region 0
        g_za[base + 32 * N_TOK * 8]   = lo;   // region 1
        g_za[base + 64 * N_TOK * 8]   = hi;   // region 2
    }
}

// ---------------- K1c: build B' from emb ----------------
// B' regions: kb [0,32): e_hi ; [32,64): e_hi ; [64,96): e_lo
__global__ void embsplit_kernel(const float* __restrict__ emb) {
    int i = blockIdx.x * blockDim.x + threadIdx.x;   // element over 8192*256
    float v = emb[i];
    int n = i >> 8, k = i & 255;
    float hi = tf32_rna(v);
    float lo = tf32_rna(v - hi);
    int kb = k >> 3;
    int base = (kb * N_E + n) * 8 + cpos(k & 7);
    g_eb[base]                  = hi;
    g_eb[base + 32 * N_E * 8]   = hi;
    g_eb[base + 64 * N_E * 8]   = lo;
}

// ---------------- K1b: exact fp32 row norms ----------------
__global__ void norms_kernel(const float* __restrict__ emb) {
    int gw   = (blockIdx.x * blockDim.x + threadIdx.x) >> 5;
    int lane = threadIdx.x & 31;
    const float* src;
    float* dst;
    if (gw < N_TOK)            { src = g_zt + gw * 256;           dst = g_znorm + gw; }
    else if (gw < N_TOK + N_E) { src = emb  + (gw - N_TOK) * 256; dst = g_enorm + (gw - N_TOK); }
    else return;

    const float4* p = (const float4*)src;
    float s = 0.f;
    #pragma unroll
    for (int i = 0; i < 2; i++) {
        float4 v = p[lane + 32 * i];
        s = fmaf(v.x, v.x, s); s = fmaf(v.y, v.y, s);
        s = fmaf(v.z, v.z, s); s = fmaf(v.w, v.w, s);
    }
    #pragma unroll
    for (int o = 16; o; o >>= 1) s += __shfl_xor_sync(0xFFFFFFFFu, s, o);
    if (lane == 0) *dst = s;
}

// ---------------- K2: mma.sync tf32 GEMM + fused argmin ----------------
// 128 CTAs, 256 threads (8 warps as 2m x 4n), warp tile 64x64.
__global__ void __launch_bounds__(256, 1) vq_mma_kernel(float* __restrict__ out_idx_f) {
    extern __shared__ float sm[];
    const uint32_t smb = smem_to_u32(sm);

    const int tid = threadIdx.x, wid = tid >> 5, lane = tid & 31;
    const int g = lane >> 2, tig = lane & 3;
    const int wm = wid >> 2, wn = wid & 3;
    const int m0 = blockIdx.x * BM;

    // preload zn for the 8 rows this thread owns
    float zn[4][2];
    #pragma unroll
    for (int t = 0; t < 4; t++) {
        zn[t][0] = g_znorm[m0 + wm * 64 + t * 16 + g];
        zn[t][1] = g_znorm[m0 + wm * 64 + t * 16 + g + 8];
    }

    float best[8];
    int   bidx[8];
    #pragma unroll
    for (int i = 0; i < 8; i++) { best[i] = __int_as_float(0x7F800000); bidx[i] = 0; }

    float acc[4][8][4];

    // stage loader: global chunk gc -> stage gc&1
    auto issue = [&](int gc) {
        int nt = gc / NCHUNK, c = gc % NCHUNK, s = gc & 1;
        int n0 = nt * BN;
        uint32_t ab = smb + (uint32_t)s * (STAGE_F * 4);
        // A: 4 blocks x 4KB contiguous
        #pragma unroll
        for (int i = 0; i < 4; i++) {
            int o = tid + 256 * i, j = o >> 8, u = o & 255;
            const float* src = g_za + ((size_t)(4 * c + j) * N_TOK + m0) * 8 + u * 4;
            cpasync16(ab + j * 4096 + u * 16, src);
        }
        // B: 4 blocks x 8KB contiguous
        uint32_t bb = ab + A_F * 4;
        #pragma unroll
        for (int i = 0; i < 8; i++) {
            int o = tid + 256 * i, j = o >> 9, u = o & 511;
            const float* src = g_eb + ((size_t)(4 * c + j) * N_E + n0) * 8 + u * 4;
            cpasync16(bb + j * 8192 + u * 16, src);
        }
        CP_COMMIT();
    };

    issue(0);

    for (int nt = 0; nt < NT; nt++) {
        #pragma unroll
        for (int t = 0; t < 4; t++)
            #pragma unroll
            for (int tn = 0; tn < 8; tn++)
                #pragma unroll
                for (int r = 0; r < 4; r++) acc[t][tn][r] = 0.f;

        for (int c = 0; c < NCHUNK; c++) {
            int gc = nt * NCHUNK + c;
            if (gc + 1 < TOTAL_GC) { issue(gc + 1); CP_WAIT(1); }
            else                   { CP_WAIT(0); }
            __syncthreads();

            const int Sf = (gc & 1) * STAGE_F;
            #pragma unroll
            for (int b = 0; b < 4; b++) {
                uint32_t ar[4][4];
                #pragma unroll
                for (int t = 0; t < 4; t++) {
                    int ro = Sf + b * 1024 + (wm * 64 + t * 16 + g) * 8 + tig * 2;
                    float2 v0 = *(const float2*)&sm[ro];
                    float2 v1 = *(const float2*)&sm[ro + 64];
                    ar[t][0] = __float_as_uint(v0.x); ar[t][2] = __float_as_uint(v0.y);
                    ar[t][1] = __float_as_uint(v1.x); ar[t][3] = __float_as_uint(v1.y);
                }
                uint32_t br[8][2];
                #pragma unroll
                for (int tn = 0; tn < 8; tn++) {
                    int bo = Sf + A_F + b * 2048 + (wn * 64 + tn * 8 + g) * 8 + tig * 2;
                    float2 v = *(const float2*)&sm[bo];
                    br[tn][0] = __float_as_uint(v.x); br[tn][1] = __float_as_uint(v.y);
                }
                #pragma unroll
                for (int t = 0; t < 4; t++)
                    #pragma unroll
                    for (int tn = 0; tn < 8; tn++)
                        MMA_TF32(acc[t][tn], ar[t][0], ar[t][1], ar[t][2], ar[t][3],
                                 br[tn][0], br[tn][1]);
            }
            __syncthreads();
        }

        // per-tile argmin fold (registers only; no smem touched)
        int n0 = nt * BN;
        #pragma unroll
        for (int t = 0; t < 4; t++) {
            #pragma unroll
            for (int tn = 0; tn < 8; tn++) {
                int cb = n0 + wn * 64 + tn * 8 + 2 * tig;
                float en0 = __ldg(&g_enorm[cb]);
                float en1 = __ldg(&g_enorm[cb + 1]);
                float s00 = fmaf(-2.f, acc[t][tn][0], zn[t][0] + en0);
                float s01 = fmaf(-2.f, acc[t][tn][1], zn[t][0] + en1);
                float s10 = fmaf(-2.f, acc[t][tn][2], zn[t][1] + en0);
                float s11 = fmaf(-2.f, acc[t][tn][3], zn[t][1] + en1);
                int s0 = t * 2, s1 = t * 2 + 1;
                if (s00 < best[s0]) { best[s0] = s00; bidx[s0] = cb; }
                if (s01 < best[s0]) { best[s0] = s01; bidx[s0] = cb + 1; }
                if (s10 < best[s1]) { best[s1] = s10; bidx[s1] = cb; }
                if (s11 < best[s1]) { best[s1] = s11; bidx[s1] = cb + 1; }
            }
        }
    }

    // merge across threads via packed (score,idx) atomicMin in smem
    __syncthreads();
    unsigned long long* sKey = (unsigned long long*)sm;
    if (tid < BM) sKey[tid] = 0xFFFFFFFFFFFFFFFFull;
    __syncthreads();
    #pragma unroll
    for (int slot = 0; slot < 8; slot++) {
        int t = slot >> 1, which = slot & 1;
        int rl = wm * 64 + t * 16 + g + which * 8;
        unsigned long long key =
            ((unsigned long long)f2o(best[slot]) << 32) | (unsigned)bidx[slot];
        atomicMin(&sKey[rl], key);
    }
    __syncthreads();
    if (tid < BM) {
        int idx = (int)(unsigned)(sKey[tid] & 0xFFFFFFFFull);
        g_idx[m0 + tid] = idx;
        out_idx_f[m0 + tid] = (float)idx;
    }
}

// ---------------- K3: gather z_q (straight-through rounding) + loss ------
__global__ void epilogue_kernel(const float* __restrict__ emb, float* __restrict__ out) {
    int bh = blockIdx.x;
    int b = bh >> 5, h = bh & 31;
    int w    = threadIdx.x >> 5;
    int lane = threadIdx.x & 31;
    int n = (b << 10) + (h << 5) + w;
    int idx = g_idx[n];

    const float4* ep = (const float4*)(emb  + idx * 256);
    const float4* zp = (const float4*)(g_zt + n   * 256);
    float ls = 0.f;
    #pragma unroll
    for (int i = 0; i < 2; i++) {
        float4 e  = ep[lane + 32 * i];
        float4 zv = zp[lane + 32 * i];
        int c = (lane + 32 * i) * 4;
        int base = (b * 256 + c) * 1024 + h * 32 + w;
        // match reference straight-through: zt + (z_q - zt), two fp32 roundings
        out[base]        = __fadd_rn(zv.x, __fsub_rn(e.x, zv.x));
        out[base + 1024] = __fadd_rn(zv.y, __fsub_rn(e.y, zv.y));
        out[base + 2048] = __fadd_rn(zv.z, __fsub_rn(e.z, zv.z));
        out[base + 3072] = __fadd_rn(zv.w, __fsub_rn(e.w, zv.w));
        float dx = e.x - zv.x, dy = e.y - zv.y, dz = e.z - zv.z, dw = e.w - zv.w;
        ls += dx * dx + dy * dy + dz * dz + dw * dw;
    }
    #pragma unroll
    for (int o = 16; o; o >>= 1) ls += __shfl_xor_sync(0xFFFFFFFFu, ls, o);
    __shared__ float red[32];
    if (lane == 0) red[w] = ls;
    __syncthreads();
    if (threadIdx.x < 32) {
        float v = red[threadIdx.x];
        #pragma unroll
        for (int o = 16; o; o >>= 1) v += __shfl_xor_sync(0xFFFFFFFFu, v, o);
        if (threadIdx.x == 0) atomicAdd(&g_loss, v);
    }
}

__global__ void finalize_kernel(float* __restrict__ out_loss) {
    out_loss[0] = 1.25f * g_loss * (1.0f / (float)ZQ_ELEMS);
}

// ---------------- launch ----------------
extern "C" void kernel_launch(void* const* d_in, const int* in_sizes, int n_in,
                              void* d_out, int out_size) {
    const float* z   = (const float*)d_in[0];
    const float* emb = (const float*)d_in[1];
    float* out = (float*)d_out;

    cudaFuncSetAttribute(vq_mma_kernel, cudaFuncAttributeMaxDynamicSharedMemorySize, SMEM_DYN);

    transpose_kernel<<<dim3(32, 8, 16), dim3(32, 8)>>>(z);
    embsplit_kernel<<<(N_E * E_DIM) / 256, 256>>>(emb);
    norms_kernel<<<(N_TOK + N_E) / 8, 256>>>(emb);
    vq_mma_kernel<<<N_TOK / BM, 256, SMEM_DYN>>>(out + ZQ_ELEMS + 1);
    epilogue_kernel<<<512, 1024>>>(emb, out);
    finalize_kernel<<<1, 1>>>(out + ZQ_ELEMS);
}